// round 11
// baseline (speedup 1.0000x reference)
#include <cuda_runtime.h>
#include <cuda_bf16.h>
#include <cstdint>
#include <cmath>
#include <cstring>

// ---------------- problem constants ----------------
#define N_NODES   2048
#define E_EDGES   8192
#define CCH       64
#define NPATH     34
#define NZ        738       // sum over paths of (2l1+1)(2l3+1)
#define NCG       3436      // sum over paths of (2l1+1)(2l2+1)(2l3+1)
#define ACC_SZ    9984      // sum over l3 of count_l3*64*(2l3+1)
#define WS_STRIDE 2176      // 34*64
#define ECAP      256
#define M_TOTAL   20447232  // sum over l3 of 2048*(2l3+1)*fanin

struct Meta {
    int2 zmeta[NZ];          // x = CG base index; y = ybase | (stride<<8) | (nm<<16)
    int  grp_path[4][16];
    int  grp_cnt[4];
    int  p_wcol[NPATH];
    int  p_xbase[NPATH];
    int  p_zbase[NPATH];
    int  p_accoff[NPATH];
    int  p_l1d[NPATH];
    int  p_l3d[NPATH];
};

__device__ Meta  g_meta;
__device__ float g_CG[NCG];
__device__ float g_M[M_TOTAL];   // scratch: per-node scattered messages, [l3][n][m][cc]

// ---------------- edge + scatter kernel ----------------
// grid: 2048 CTAs (one per destination node), 256 threads.
// smem: acc[9984] | xs[1024] | zsh[744] | ysh[16] | elist[256]  (scan buffer aliases zsh)
__global__ __launch_bounds__(256)
void edge_kernel(const float* __restrict__ x0, const float* __restrict__ x1,
                 const float* __restrict__ x2, const float* __restrict__ x3,
                 const float* __restrict__ y0, const float* __restrict__ y1,
                 const float* __restrict__ y2, const float* __restrict__ y3,
                 const float* __restrict__ ws, const int* __restrict__ eidx)
{
    extern __shared__ float sm[];
    float* acc  = sm;                    // 9984
    float* xs   = acc + ACC_SZ;          // 1024
    float* zsh  = xs + 1024;             // 744
    float* ysh  = zsh + 744;             // 16
    int*   elist = (int*)(ysh + 16);     // 256 ints
    int*   scanb = (int*)zsh;            // alias, used only before zsh is live
    __shared__ int s_ne;

    const int node = blockIdx.x;
    const int tid  = threadIdx.x;
    const int* srcA = eidx;
    const int* dstA = eidx + E_EDGES;

    for (int i = tid; i < ACC_SZ; i += 256) acc[i] = 0.f;

    // ---- deterministic compaction of in-edges ----
    int cnt = 0;
    #pragma unroll
    for (int j = 0; j < E_EDGES / 256; j++)
        cnt += (dstA[tid + j * 256] == node) ? 1 : 0;

    scanb[tid] = cnt;
    __syncthreads();
    for (int off = 1; off < 256; off <<= 1) {
        int v = (tid >= off) ? scanb[tid - off] : 0;
        __syncthreads();
        scanb[tid] += v;
        __syncthreads();
    }
    int pos = scanb[tid] - cnt;
    if (tid == 255) s_ne = (scanb[255] < ECAP) ? scanb[255] : ECAP;
    __syncthreads();
    #pragma unroll
    for (int j = 0; j < E_EDGES / 256; j++) {
        int e = tid + j * 256;
        if (dstA[e] == node) { if (pos < ECAP) elist[pos] = e; pos++; }
    }
    __syncthreads();
    const int ne = s_ne;

    const int g = tid >> 6;
    const int c = tid & 63;

    for (int k = 0; k < ne; k++) {
        __syncthreads();                       // previous iteration's readers done
        const int e = elist[k];
        const int s = srcA[e];

        // stage y (16 floats) and x[src] (1024 floats) into smem, coalesced
        if (tid < 16) {
            float v;
            if (tid == 0)      v = y0[e];
            else if (tid < 4)  v = y1[e * 3 + (tid - 1)];
            else if (tid < 9)  v = y2[e * 5 + (tid - 4)];
            else               v = y3[e * 7 + (tid - 9)];
            ysh[tid] = v;
        }
        #pragma unroll
        for (int j = 0; j < 4; j++) {
            int idx = tid + j * 256;
            float v;
            if (idx < 64)        v = x0[s * 64  + idx];
            else if (idx < 256)  v = x1[s * 192 + (idx - 64)];
            else if (idx < 576)  v = x2[s * 320 + (idx - 256)];
            else                 v = x3[s * 448 + (idx - 576)];
            xs[idx] = v;
        }
        __syncthreads();

        // z_i[l,n] = sum_m CG_i[l,m,n] * y[m]   (channel independent, once per edge)
        for (int j = tid; j < NZ; j += 256) {
            int2 mz = g_meta.zmeta[j];
            int base = mz.x;
            int yb = mz.y & 0xff, st = (mz.y >> 8) & 0xff, nm = (mz.y >> 16) & 0xff;
            float sacc = 0.f;
            for (int q = 0; q < nm; q++) sacc += g_CG[base + q * st] * ysh[yb + q];
            zsh[j] = sacc;
        }
        __syncthreads();

        // main contraction: acc[cc, n] += ws[e, i*64+c] * sum_l x[c,l] z_i[l,n]
        const float* wrow = ws + (size_t)e * WS_STRIDE;
        const int np = g_meta.grp_cnt[g];
        for (int pp = 0; pp < np; pp++) {
            const int p   = g_meta.grp_path[g][pp];
            const int l1d = g_meta.p_l1d[p];
            const int l3d = g_meta.p_l3d[p];
            const float w = wrow[g_meta.p_wcol[p] + c];
            const int xb  = g_meta.p_xbase[p] + c * l1d;
            const int zb  = g_meta.p_zbase[p];
            const int ab  = g_meta.p_accoff[p] + c * l3d;
            switch (l1d) {
            case 1: {
                float a0 = xs[xb];
                for (int n = 0; n < l3d; n++)
                    acc[ab + n] += w * (a0 * zsh[zb + n]);
            } break;
            case 3: {
                float a0 = xs[xb], a1 = xs[xb + 1], a2 = xs[xb + 2];
                for (int n = 0; n < l3d; n++) {
                    float d = a0 * zsh[zb + n] + a1 * zsh[zb + l3d + n]
                            + a2 * zsh[zb + 2 * l3d + n];
                    acc[ab + n] += w * d;
                }
            } break;
            case 5: {
                float a0 = xs[xb], a1 = xs[xb + 1], a2 = xs[xb + 2],
                      a3 = xs[xb + 3], a4 = xs[xb + 4];
                for (int n = 0; n < l3d; n++) {
                    float d = a0 * zsh[zb + n] + a1 * zsh[zb + l3d + n]
                            + a2 * zsh[zb + 2 * l3d + n] + a3 * zsh[zb + 3 * l3d + n]
                            + a4 * zsh[zb + 4 * l3d + n];
                    acc[ab + n] += w * d;
                }
            } break;
            default: {
                float a0 = xs[xb], a1 = xs[xb + 1], a2 = xs[xb + 2],
                      a3 = xs[xb + 3], a4 = xs[xb + 4], a5 = xs[xb + 5],
                      a6 = xs[xb + 6];
                for (int n = 0; n < l3d; n++) {
                    float d = a0 * zsh[zb + n] + a1 * zsh[zb + l3d + n]
                            + a2 * zsh[zb + 2 * l3d + n] + a3 * zsh[zb + 3 * l3d + n]
                            + a4 * zsh[zb + 4 * l3d + n] + a5 * zsh[zb + 5 * l3d + n]
                            + a6 * zsh[zb + 6 * l3d + n];
                    acc[ab + n] += w * d;
                }
            } break;
            }
        }
    }
    __syncthreads();

    // writeout: M[l3][node][m][cc]  (cc contiguous -> GEMM K-major rows)
    const int  l3dA[4]  = {1, 3, 5, 7};
    const int  faninA[4] = {256, 576, 704, 640};
    const int  accbA[4] = {0, 256, 1984, 5504};
    const long mbA[4]   = {0L, 524288L, 4063232L, 11272192L};
    for (int l3 = 0; l3 < 4; l3++) {
        const int  ld = l3dA[l3], fi = faninA[l3], ab = accbA[l3];
        const long base = mbA[l3] + (long)node * ld * fi;
        const int  sz = ld * fi;
        for (int idx = tid; idx < sz; idx += 256) {
            int cc = idx % fi;
            int m  = idx / fi;
            g_M[base + idx] = acc[ab + cc * ld + m];
        }
    }
}

// ---------------- output GEMM kernel ----------------
// For each l3: out[n,h,m] = sum_cc M[n,m,cc] * W_l3[cc,h]
// rows r = n*(2l3+1)+m are contiguous length-fanin rows of g_M.
// Tiles: BM=64, BN=64(=H), BK=32; 256 threads, 4x4 per thread.
__global__ __launch_bounds__(256)
void gemm_kernel(const float* __restrict__ W0, const float* __restrict__ W1,
                 const float* __restrict__ W2, const float* __restrict__ W3,
                 float* __restrict__ out)
{
    __shared__ float As[32][68];   // transposed A tile, padded (16B-aligned rows)
    __shared__ float Bs[32][64];

    const int blk = blockIdx.x, tid = threadIdx.x;
    int l3, t0;
    if (blk < 32)       { l3 = 0; t0 = 0; }
    else if (blk < 128) { l3 = 1; t0 = 32; }
    else if (blk < 288) { l3 = 2; t0 = 128; }
    else                { l3 = 3; t0 = 288; }
    const int rowTile = blk - t0;

    const int  KA[4] = {256, 576, 704, 640};
    const long MB[4] = {0L, 524288L, 4063232L, 11272192L};
    const long OB[4] = {0L, 131072L, 524288L, 1179648L};
    const int  K  = KA[l3];
    const int  ld = 2 * l3 + 1;
    const float* A = g_M + MB[l3] + (long)rowTile * 64 * K;
    const float* B = (l3 == 0) ? W0 : (l3 == 1) ? W1 : (l3 == 2) ? W2 : W3;
    float* Ob = out + OB[l3];

    const int tr = (tid >> 4) << 2, tc = (tid & 15) << 2;
    const int arow = tid >> 2, ac0 = (tid & 3) << 3;
    const int brow = tid >> 3, bc0 = (tid & 7) << 3;

    float ac[4][4] = {};

    for (int k0 = 0; k0 < K; k0 += 32) {
        float4 a0 = *(const float4*)(A + (long)arow * K + k0 + ac0);
        float4 a1 = *(const float4*)(A + (long)arow * K + k0 + ac0 + 4);
        As[ac0 + 0][arow] = a0.x; As[ac0 + 1][arow] = a0.y;
        As[ac0 + 2][arow] = a0.z; As[ac0 + 3][arow] = a0.w;
        As[ac0 + 4][arow] = a1.x; As[ac0 + 5][arow] = a1.y;
        As[ac0 + 6][arow] = a1.z; As[ac0 + 7][arow] = a1.w;
        *(float4*)&Bs[brow][bc0]     = *(const float4*)(B + (long)(k0 + brow) * 64 + bc0);
        *(float4*)&Bs[brow][bc0 + 4] = *(const float4*)(B + (long)(k0 + brow) * 64 + bc0 + 4);
        __syncthreads();
        #pragma unroll
        for (int k = 0; k < 32; k++) {
            float4 av = *(const float4*)&As[k][tr];
            float4 bv = *(const float4*)&Bs[k][tc];
            ac[0][0] += av.x * bv.x; ac[0][1] += av.x * bv.y;
            ac[0][2] += av.x * bv.z; ac[0][3] += av.x * bv.w;
            ac[1][0] += av.y * bv.x; ac[1][1] += av.y * bv.y;
            ac[1][2] += av.y * bv.z; ac[1][3] += av.y * bv.w;
            ac[2][0] += av.z * bv.x; ac[2][1] += av.z * bv.y;
            ac[2][2] += av.z * bv.z; ac[2][3] += av.z * bv.w;
            ac[3][0] += av.w * bv.x; ac[3][1] += av.w * bv.y;
            ac[3][2] += av.w * bv.z; ac[3][3] += av.w * bv.w;
        }
        __syncthreads();
    }

    #pragma unroll
    for (int i = 0; i < 4; i++) {
        int r = rowTile * 64 + tr + i;
        int n = r / ld, m = r - n * ld;
        float* op = Ob + (long)n * 64 * ld + m;
        #pragma unroll
        for (int j = 0; j < 4; j++) op[(long)(tc + j) * ld] = ac[i][j];
    }
}

// ---------------- host: regenerate numpy CG constants + metadata ----------------
static void build_host_tables(float* cg, Meta* M)
{
    // MT19937 seeded exactly like np.random.RandomState(1234)
    uint32_t mt[624]; int mti;
    uint32_t sd = 1234u;
    for (int i = 0; i < 624; i++) {
        mt[i] = sd;
        sd = 1812433253u * (sd ^ (sd >> 30)) + (uint32_t)i + 1u;
    }
    mti = 624;
    auto mt_next = [&]() -> uint32_t {
        if (mti >= 624) {
            for (int i = 0; i < 624; i++) {
                uint32_t y = (mt[i] & 0x80000000u) | (mt[(i + 1) % 624] & 0x7fffffffu);
                mt[i] = mt[(i + 397) % 624] ^ (y >> 1) ^ ((y & 1u) ? 0x9908b0dfu : 0u);
            }
            mti = 0;
        }
        uint32_t y = mt[mti++];
        y ^= y >> 11; y ^= (y << 7) & 0x9d2c5680u;
        y ^= (y << 15) & 0xefc60000u; y ^= y >> 18;
        return y;
    };
    auto rk_double = [&]() -> double {
        uint32_t a = mt_next() >> 5, b = mt_next() >> 6;
        return ((double)a * 67108864.0 + (double)b) / 9007199254740992.0;
    };
    bool   has_g = false;
    double gch = 0.0;
    auto gauss = [&]() -> double {
        if (has_g) { has_g = false; return gch; }
        double x1, x2, r2;
        do {
            x1 = 2.0 * rk_double() - 1.0;
            x2 = 2.0 * rk_double() - 1.0;
            r2 = x1 * x1 + x2 * x2;
        } while (r2 >= 1.0 || r2 == 0.0);
        double f = sqrt(-2.0 * log(r2) / r2);
        gch = f * x1; has_g = true;
        return f * x2;
    };

    // enumerate COMBS
    int l1a[NPATH], l2a[NPATH], l3a[NPATH], npc = 0;
    for (int l1 = 0; l1 <= 3; l1++)
        for (int l2 = 0; l2 <= 3; l2++) {
            int lo = (l1 > l2) ? (l1 - l2) : (l2 - l1);
            int hi = (l1 + l2 < 3) ? (l1 + l2) : 3;
            for (int l3 = lo; l3 <= hi; l3++) {
                l1a[npc] = l1; l2a[npc] = l2; l3a[npc] = l3; npc++;
            }
        }

    const int accb[4]  = {0, 256, 1984, 5504};
    const int ybase[4] = {0, 1, 4, 9};
    const int xbase[4] = {0, 64, 256, 576};
    int cgoff = 0, zoff = 0, zm = 0;
    int rank[4] = {0, 0, 0, 0};
    for (int p = 0; p < NPATH; p++) {
        int d1 = 2 * l1a[p] + 1, d2 = 2 * l2a[p] + 1, d3 = 2 * l3a[p] + 1;
        int n = d1 * d2 * d3;
        for (int t = 0; t < n; t++) cg[cgoff + t] = (float)(gauss() * 0.2);
        M->p_wcol[p]   = p * 64;
        M->p_xbase[p]  = xbase[l1a[p]];
        M->p_zbase[p]  = zoff;
        M->p_accoff[p] = accb[l3a[p]] + rank[l3a[p]] * 64 * d3;
        M->p_l1d[p]    = d1;
        M->p_l3d[p]    = d3;
        for (int l = 0; l < d1; l++)
            for (int nn = 0; nn < d3; nn++) {
                M->zmeta[zm].x = cgoff + l * d2 * d3 + nn;
                M->zmeta[zm].y = ybase[l2a[p]] | (d3 << 8) | (d2 << 16);
                zm++;
            }
        rank[l3a[p]]++;
        cgoff += n;
        zoff  += d1 * d3;
    }

    // greedy load-balanced partition of paths into 4 thread groups
    int order[NPATH];
    for (int i = 0; i < NPATH; i++) order[i] = i;
    for (int i = 0; i < NPATH; i++)
        for (int j = i + 1; j < NPATH; j++) {
            int ci = M->p_l1d[order[i]] * M->p_l3d[order[i]];
            int cj = M->p_l1d[order[j]] * M->p_l3d[order[j]];
            if (cj > ci) { int t = order[i]; order[i] = order[j]; order[j] = t; }
        }
    int load[4] = {0, 0, 0, 0};
    for (int g = 0; g < 4; g++) M->grp_cnt[g] = 0;
    for (int i = 0; i < NPATH; i++) {
        int best = 0;
        for (int g = 1; g < 4; g++)
            if (M->grp_cnt[g] < 16 &&
                (M->grp_cnt[best] >= 16 || load[g] < load[best])) best = g;
        int p = order[i];
        M->grp_path[best][M->grp_cnt[best]++] = p;
        load[best] += M->p_l1d[p] * M->p_l3d[p];
    }
}

extern "C" void kernel_launch(void* const* d_in, const int* in_sizes, int n_in,
                              void* d_out, int out_size)
{
    static float h_cg[NCG];
    static Meta  h_meta;
    build_host_tables(h_cg, &h_meta);

    cudaMemcpyToSymbolAsync(g_CG, h_cg, sizeof(h_cg), 0, cudaMemcpyHostToDevice, 0);
    cudaMemcpyToSymbolAsync(g_meta, &h_meta, sizeof(Meta), 0, cudaMemcpyHostToDevice, 0);

    const float *x[4], *y[4], *wl[4], *wsP;
    const int* ei;
    if (n_in >= 14 && in_sizes[1] == E_EDGES) {
        // dict order: x0,y0,w0, x1,y1,w1, x2,y2,w2, x3,y3,w3, ws, edge_index
        for (int l = 0; l < 4; l++) {
            x[l]  = (const float*)d_in[3 * l + 0];
            y[l]  = (const float*)d_in[3 * l + 1];
            wl[l] = (const float*)d_in[3 * l + 2];
        }
        wsP = (const float*)d_in[12];
        ei  = (const int*)d_in[13];
    } else {
        // signature order: x0..x3, y0..y3, ws, w0..w3, edge_index
        for (int l = 0; l < 4; l++) {
            x[l]  = (const float*)d_in[l];
            y[l]  = (const float*)d_in[4 + l];
            wl[l] = (const float*)d_in[9 + l];
        }
        wsP = (const float*)d_in[8];
        ei  = (const int*)d_in[13];
    }

    const size_t smemB = (ACC_SZ + 1024 + 744 + 16) * sizeof(float) + ECAP * sizeof(int);
    edge_kernel<<<N_NODES, 256, smemB>>>(x[0], x[1], x[2], x[3],
                                         y[0], y[1], y[2], y[3], wsP, ei);
    gemm_kernel<<<512, 256>>>(wl[0], wl[1], wl[2], wl[3], (float*)d_out);
    (void)out_size;
}

// round 12
// speedup vs baseline: 1.0003x; 1.0003x over previous
#include <cuda_runtime.h>
#include <cuda_bf16.h>
#include <cstdint>
#include <cmath>
#include <cstring>

// ---------------- problem constants ----------------
#define N_NODES   2048
#define E_EDGES   8192
#define CCH       64
#define NPATH     34
#define NZ        738       // sum over paths of (2l1+1)(2l3+1)
#define NCG       3436      // sum over paths of (2l1+1)(2l2+1)(2l3+1)
#define ACC_SZ    9984      // sum over l3 of count_l3*64*(2l3+1)
#define WS_STRIDE 2176      // 34*64
#define ECAP      256
#define M_TOTAL   20447232  // sum over l3 of 2048*(2l3+1)*fanin

struct Meta {
    int2 zmeta[NZ];          // x = CG base index; y = ybase | (stride<<8) | (nm<<16)
    int  grp_path[4][16];
    int  grp_cnt[4];
    int  p_wcol[NPATH];
    int  p_xbase[NPATH];
    int  p_zbase[NPATH];
    int  p_accoff[NPATH];
    int  p_l1d[NPATH];
    int  p_l3d[NPATH];
};

__device__ Meta  g_meta;
__device__ float g_CG[NCG];
__device__ float g_M[M_TOTAL];   // scratch: per-node scattered messages, [l3][n][m][cc]

// ---------------- edge + scatter kernel ----------------
// grid: 2048 CTAs (one per destination node), 256 threads.
// smem: acc[9984] | xs[1024] | zsh[744] | ysh[16] | elist[256]  (scan buffer aliases zsh)
__global__ __launch_bounds__(256)
void edge_kernel(const float* __restrict__ x0, const float* __restrict__ x1,
                 const float* __restrict__ x2, const float* __restrict__ x3,
                 const float* __restrict__ y0, const float* __restrict__ y1,
                 const float* __restrict__ y2, const float* __restrict__ y3,
                 const float* __restrict__ ws, const int* __restrict__ eidx)
{
    extern __shared__ float sm[];
    float* acc  = sm;                    // 9984
    float* xs   = acc + ACC_SZ;          // 1024
    float* zsh  = xs + 1024;             // 744
    float* ysh  = zsh + 744;             // 16
    int*   elist = (int*)(ysh + 16);     // 256 ints
    int*   scanb = (int*)zsh;            // alias, used only before zsh is live
    __shared__ int s_ne;

    const int node = blockIdx.x;
    const int tid  = threadIdx.x;
    const int* srcA = eidx;
    const int* dstA = eidx + E_EDGES;

    for (int i = tid; i < ACC_SZ; i += 256) acc[i] = 0.f;

    // ---- deterministic compaction of in-edges ----
    int cnt = 0;
    #pragma unroll
    for (int j = 0; j < E_EDGES / 256; j++)
        cnt += (dstA[tid + j * 256] == node) ? 1 : 0;

    scanb[tid] = cnt;
    __syncthreads();
    for (int off = 1; off < 256; off <<= 1) {
        int v = (tid >= off) ? scanb[tid - off] : 0;
        __syncthreads();
        scanb[tid] += v;
        __syncthreads();
    }
    int pos = scanb[tid] - cnt;
    if (tid == 255) s_ne = (scanb[255] < ECAP) ? scanb[255] : ECAP;
    __syncthreads();
    #pragma unroll
    for (int j = 0; j < E_EDGES / 256; j++) {
        int e = tid + j * 256;
        if (dstA[e] == node) { if (pos < ECAP) elist[pos] = e; pos++; }
    }
    __syncthreads();
    const int ne = s_ne;

    const int g = tid >> 6;
    const int c = tid & 63;

    for (int k = 0; k < ne; k++) {
        __syncthreads();                       // previous iteration's readers done
        const int e = elist[k];
        const int s = srcA[e];

        // stage y (16 floats) and x[src] (1024 floats) into smem, coalesced
        if (tid < 16) {
            float v;
            if (tid == 0)      v = y0[e];
            else if (tid < 4)  v = y1[e * 3 + (tid - 1)];
            else if (tid < 9)  v = y2[e * 5 + (tid - 4)];
            else               v = y3[e * 7 + (tid - 9)];
            ysh[tid] = v;
        }
        #pragma unroll
        for (int j = 0; j < 4; j++) {
            int idx = tid + j * 256;
            float v;
            if (idx < 64)        v = x0[s * 64  + idx];
            else if (idx < 256)  v = x1[s * 192 + (idx - 64)];
            else if (idx < 576)  v = x2[s * 320 + (idx - 256)];
            else                 v = x3[s * 448 + (idx - 576)];
            xs[idx] = v;
        }
        __syncthreads();

        // z_i[l,n] = sum_m CG_i[l,m,n] * y[m]   (channel independent, once per edge)
        for (int j = tid; j < NZ; j += 256) {
            int2 mz = g_meta.zmeta[j];
            int base = mz.x;
            int yb = mz.y & 0xff, st = (mz.y >> 8) & 0xff, nm = (mz.y >> 16) & 0xff;
            float sacc = 0.f;
            for (int q = 0; q < nm; q++) sacc += g_CG[base + q * st] * ysh[yb + q];
            zsh[j] = sacc;
        }
        __syncthreads();

        // main contraction: acc[cc, n] += ws[e, i*64+c] * sum_l x[c,l] z_i[l,n]
        const float* wrow = ws + (size_t)e * WS_STRIDE;
        const int np = g_meta.grp_cnt[g];
        for (int pp = 0; pp < np; pp++) {
            const int p   = g_meta.grp_path[g][pp];
            const int l1d = g_meta.p_l1d[p];
            const int l3d = g_meta.p_l3d[p];
            const float w = wrow[g_meta.p_wcol[p] + c];
            const int xb  = g_meta.p_xbase[p] + c * l1d;
            const int zb  = g_meta.p_zbase[p];
            const int ab  = g_meta.p_accoff[p] + c * l3d;
            switch (l1d) {
            case 1: {
                float a0 = xs[xb];
                for (int n = 0; n < l3d; n++)
                    acc[ab + n] += w * (a0 * zsh[zb + n]);
            } break;
            case 3: {
                float a0 = xs[xb], a1 = xs[xb + 1], a2 = xs[xb + 2];
                for (int n = 0; n < l3d; n++) {
                    float d = a0 * zsh[zb + n] + a1 * zsh[zb + l3d + n]
                            + a2 * zsh[zb + 2 * l3d + n];
                    acc[ab + n] += w * d;
                }
            } break;
            case 5: {
                float a0 = xs[xb], a1 = xs[xb + 1], a2 = xs[xb + 2],
                      a3 = xs[xb + 3], a4 = xs[xb + 4];
                for (int n = 0; n < l3d; n++) {
                    float d = a0 * zsh[zb + n] + a1 * zsh[zb + l3d + n]
                            + a2 * zsh[zb + 2 * l3d + n] + a3 * zsh[zb + 3 * l3d + n]
                            + a4 * zsh[zb + 4 * l3d + n];
                    acc[ab + n] += w * d;
                }
            } break;
            default: {
                float a0 = xs[xb], a1 = xs[xb + 1], a2 = xs[xb + 2],
                      a3 = xs[xb + 3], a4 = xs[xb + 4], a5 = xs[xb + 5],
                      a6 = xs[xb + 6];
                for (int n = 0; n < l3d; n++) {
                    float d = a0 * zsh[zb + n] + a1 * zsh[zb + l3d + n]
                            + a2 * zsh[zb + 2 * l3d + n] + a3 * zsh[zb + 3 * l3d + n]
                            + a4 * zsh[zb + 4 * l3d + n] + a5 * zsh[zb + 5 * l3d + n]
                            + a6 * zsh[zb + 6 * l3d + n];
                    acc[ab + n] += w * d;
                }
            } break;
            }
        }
    }
    __syncthreads();

    // writeout: M[l3][node][m][cc]  (cc contiguous -> GEMM K-major rows)
    const int  l3dA[4]  = {1, 3, 5, 7};
    const int  faninA[4] = {256, 576, 704, 640};
    const int  accbA[4] = {0, 256, 1984, 5504};
    const long mbA[4]   = {0L, 524288L, 4063232L, 11272192L};
    for (int l3 = 0; l3 < 4; l3++) {
        const int  ld = l3dA[l3], fi = faninA[l3], ab = accbA[l3];
        const long base = mbA[l3] + (long)node * ld * fi;
        const int  sz = ld * fi;
        for (int idx = tid; idx < sz; idx += 256) {
            int cc = idx % fi;
            int m  = idx / fi;
            g_M[base + idx] = acc[ab + cc * ld + m];
        }
    }
}

// ---------------- output GEMM kernel ----------------
// For each l3: out[n,h,m] = sum_cc M[n,m,cc] * W_l3[cc,h]
// rows r = n*(2l3+1)+m are contiguous length-fanin rows of g_M.
// Tiles: BM=64, BN=64(=H), BK=32; 256 threads, 4x4 per thread.
__global__ __launch_bounds__(256)
void gemm_kernel(const float* __restrict__ W0, const float* __restrict__ W1,
                 const float* __restrict__ W2, const float* __restrict__ W3,
                 float* __restrict__ out)
{
    __shared__ float As[32][68];   // transposed A tile, padded (16B-aligned rows)
    __shared__ float Bs[32][64];

    const int blk = blockIdx.x, tid = threadIdx.x;
    int l3, t0;
    if (blk < 32)       { l3 = 0; t0 = 0; }
    else if (blk < 128) { l3 = 1; t0 = 32; }
    else if (blk < 288) { l3 = 2; t0 = 128; }
    else                { l3 = 3; t0 = 288; }
    const int rowTile = blk - t0;

    const int  KA[4] = {256, 576, 704, 640};
    const long MB[4] = {0L, 524288L, 4063232L, 11272192L};
    const long OB[4] = {0L, 131072L, 524288L, 1179648L};
    const int  K  = KA[l3];
    const int  ld = 2 * l3 + 1;
    const float* A = g_M + MB[l3] + (long)rowTile * 64 * K;
    const float* B = (l3 == 0) ? W0 : (l3 == 1) ? W1 : (l3 == 2) ? W2 : W3;
    float* Ob = out + OB[l3];

    const int tr = (tid >> 4) << 2, tc = (tid & 15) << 2;
    const int arow = tid >> 2, ac0 = (tid & 3) << 3;
    const int brow = tid >> 3, bc0 = (tid & 7) << 3;

    float ac[4][4] = {};

    for (int k0 = 0; k0 < K; k0 += 32) {
        float4 a0 = *(const float4*)(A + (long)arow * K + k0 + ac0);
        float4 a1 = *(const float4*)(A + (long)arow * K + k0 + ac0 + 4);
        As[ac0 + 0][arow] = a0.x; As[ac0 + 1][arow] = a0.y;
        As[ac0 + 2][arow] = a0.z; As[ac0 + 3][arow] = a0.w;
        As[ac0 + 4][arow] = a1.x; As[ac0 + 5][arow] = a1.y;
        As[ac0 + 6][arow] = a1.z; As[ac0 + 7][arow] = a1.w;
        *(float4*)&Bs[brow][bc0]     = *(const float4*)(B + (long)(k0 + brow) * 64 + bc0);
        *(float4*)&Bs[brow][bc0 + 4] = *(const float4*)(B + (long)(k0 + brow) * 64 + bc0 + 4);
        __syncthreads();
        #pragma unroll
        for (int k = 0; k < 32; k++) {
            float4 av = *(const float4*)&As[k][tr];
            float4 bv = *(const float4*)&Bs[k][tc];
            ac[0][0] += av.x * bv.x; ac[0][1] += av.x * bv.y;
            ac[0][2] += av.x * bv.z; ac[0][3] += av.x * bv.w;
            ac[1][0] += av.y * bv.x; ac[1][1] += av.y * bv.y;
            ac[1][2] += av.y * bv.z; ac[1][3] += av.y * bv.w;
            ac[2][0] += av.z * bv.x; ac[2][1] += av.z * bv.y;
            ac[2][2] += av.z * bv.z; ac[2][3] += av.z * bv.w;
            ac[3][0] += av.w * bv.x; ac[3][1] += av.w * bv.y;
            ac[3][2] += av.w * bv.z; ac[3][3] += av.w * bv.w;
        }
        __syncthreads();
    }

    #pragma unroll
    for (int i = 0; i < 4; i++) {
        int r = rowTile * 64 + tr + i;
        int n = r / ld, m = r - n * ld;
        float* op = Ob + (long)n * 64 * ld + m;
        #pragma unroll
        for (int j = 0; j < 4; j++) op[(long)(tc + j) * ld] = ac[i][j];
    }
}

// ---------------- host: regenerate numpy CG constants + metadata ----------------
static void build_host_tables(float* cg, Meta* M)
{
    // MT19937 seeded exactly like np.random.RandomState(1234)
    uint32_t mt[624]; int mti;
    uint32_t sd = 1234u;
    for (int i = 0; i < 624; i++) {
        mt[i] = sd;
        sd = 1812433253u * (sd ^ (sd >> 30)) + (uint32_t)i + 1u;
    }
    mti = 624;
    auto mt_next = [&]() -> uint32_t {
        if (mti >= 624) {
            for (int i = 0; i < 624; i++) {
                uint32_t y = (mt[i] & 0x80000000u) | (mt[(i + 1) % 624] & 0x7fffffffu);
                mt[i] = mt[(i + 397) % 624] ^ (y >> 1) ^ ((y & 1u) ? 0x9908b0dfu : 0u);
            }
            mti = 0;
        }
        uint32_t y = mt[mti++];
        y ^= y >> 11; y ^= (y << 7) & 0x9d2c5680u;
        y ^= (y << 15) & 0xefc60000u; y ^= y >> 18;
        return y;
    };
    auto rk_double = [&]() -> double {
        uint32_t a = mt_next() >> 5, b = mt_next() >> 6;
        return ((double)a * 67108864.0 + (double)b) / 9007199254740992.0;
    };
    bool   has_g = false;
    double gch = 0.0;
    auto gauss = [&]() -> double {
        if (has_g) { has_g = false; return gch; }
        double x1, x2, r2;
        do {
            x1 = 2.0 * rk_double() - 1.0;
            x2 = 2.0 * rk_double() - 1.0;
            r2 = x1 * x1 + x2 * x2;
        } while (r2 >= 1.0 || r2 == 0.0);
        double f = sqrt(-2.0 * log(r2) / r2);
        gch = f * x1; has_g = true;
        return f * x2;
    };

    // enumerate COMBS
    int l1a[NPATH], l2a[NPATH], l3a[NPATH], npc = 0;
    for (int l1 = 0; l1 <= 3; l1++)
        for (int l2 = 0; l2 <= 3; l2++) {
            int lo = (l1 > l2) ? (l1 - l2) : (l2 - l1);
            int hi = (l1 + l2 < 3) ? (l1 + l2) : 3;
            for (int l3 = lo; l3 <= hi; l3++) {
                l1a[npc] = l1; l2a[npc] = l2; l3a[npc] = l3; npc++;
            }
        }

    const int accb[4]  = {0, 256, 1984, 5504};
    const int ybase[4] = {0, 1, 4, 9};
    const int xbase[4] = {0, 64, 256, 576};
    int cgoff = 0, zoff = 0, zm = 0;
    int rank[4] = {0, 0, 0, 0};
    for (int p = 0; p < NPATH; p++) {
        int d1 = 2 * l1a[p] + 1, d2 = 2 * l2a[p] + 1, d3 = 2 * l3a[p] + 1;
        int n = d1 * d2 * d3;
        for (int t = 0; t < n; t++) cg[cgoff + t] = (float)(gauss() * 0.2);
        M->p_wcol[p]   = p * 64;
        M->p_xbase[p]  = xbase[l1a[p]];
        M->p_zbase[p]  = zoff;
        M->p_accoff[p] = accb[l3a[p]] + rank[l3a[p]] * 64 * d3;
        M->p_l1d[p]    = d1;
        M->p_l3d[p]    = d3;
        for (int l = 0; l < d1; l++)
            for (int nn = 0; nn < d3; nn++) {
                M->zmeta[zm].x = cgoff + l * d2 * d3 + nn;
                M->zmeta[zm].y = ybase[l2a[p]] | (d3 << 8) | (d2 << 16);
                zm++;
            }
        rank[l3a[p]]++;
        cgoff += n;
        zoff  += d1 * d3;
    }

    // greedy load-balanced partition of paths into 4 thread groups
    int order[NPATH];
    for (int i = 0; i < NPATH; i++) order[i] = i;
    for (int i = 0; i < NPATH; i++)
        for (int j = i + 1; j < NPATH; j++) {
            int ci = M->p_l1d[order[i]] * M->p_l3d[order[i]];
            int cj = M->p_l1d[order[j]] * M->p_l3d[order[j]];
            if (cj > ci) { int t = order[i]; order[i] = order[j]; order[j] = t; }
        }
    int load[4] = {0, 0, 0, 0};
    for (int g = 0; g < 4; g++) M->grp_cnt[g] = 0;
    for (int i = 0; i < NPATH; i++) {
        int best = 0;
        for (int g = 1; g < 4; g++)
            if (M->grp_cnt[g] < 16 &&
                (M->grp_cnt[best] >= 16 || load[g] < load[best])) best = g;
        int p = order[i];
        M->grp_path[best][M->grp_cnt[best]++] = p;
        load[best] += M->p_l1d[p] * M->p_l3d[p];
    }
}

extern "C" void kernel_launch(void* const* d_in, const int* in_sizes, int n_in,
                              void* d_out, int out_size)
{
    static float h_cg[NCG];
    static Meta  h_meta;
    build_host_tables(h_cg, &h_meta);

    cudaMemcpyToSymbolAsync(g_CG, h_cg, sizeof(h_cg), 0, cudaMemcpyHostToDevice, 0);
    cudaMemcpyToSymbolAsync(g_meta, &h_meta, sizeof(Meta), 0, cudaMemcpyHostToDevice, 0);

    const float *x[4], *y[4], *wl[4], *wsP;
    const int* ei;
    if (n_in >= 14 && in_sizes[1] == E_EDGES) {
        // dict order: x0,y0,w0, x1,y1,w1, x2,y2,w2, x3,y3,w3, ws, edge_index
        for (int l = 0; l < 4; l++) {
            x[l]  = (const float*)d_in[3 * l + 0];
            y[l]  = (const float*)d_in[3 * l + 1];
            wl[l] = (const float*)d_in[3 * l + 2];
        }
        wsP = (const float*)d_in[12];
        ei  = (const int*)d_in[13];
    } else {
        // signature order: x0..x3, y0..y3, ws, w0..w3, edge_index
        for (int l = 0; l < 4; l++) {
            x[l]  = (const float*)d_in[l];
            y[l]  = (const float*)d_in[4 + l];
            wl[l] = (const float*)d_in[9 + l];
        }
        wsP = (const float*)d_in[8];
        ei  = (const int*)d_in[13];
    }

    const size_t smemB = (ACC_SZ + 1024 + 744 + 16) * sizeof(float) + ECAP * sizeof(int);
    edge_kernel<<<N_NODES, 256, smemB>>>(x[0], x[1], x[2], x[3],
                                         y[0], y[1], y[2], y[3], wsP, ei);
    gemm_kernel<<<512, 256>>>(wl[0], wl[1], wl[2], wl[3], (float*)d_out);
    (void)out_size;
}

// round 13
// speedup vs baseline: 1.3257x; 1.3253x over previous
#include <cuda_runtime.h>
#include <cuda_bf16.h>
#include <cstdint>
#include <cmath>
#include <cstring>

// ---------------- problem constants ----------------
#define N_NODES   2048
#define E_EDGES   8192
#define NPATH     34
#define NZ        738
#define NCG       3436
#define WS_STRIDE 2176
#define ECAP      256
#define ZPAD      752       // padded per-edge z row (738 used), 16B multiple
#define M_TOTAL   20447232

// ---------------- compile-time path tables ----------------
struct Tables {
    int l1[NPATH], l2[NPATH], l3[NPATH], cgo[NPATH], zo[NPATH], rk[NPATH];
    constexpr Tables() : l1(), l2(), l3(), cgo(), zo(), rk() {
        int p = 0, cg = 0, z = 0; int rank[4] = {0, 0, 0, 0};
        for (int a = 0; a < 4; a++)
            for (int b = 0; b < 4; b++) {
                int lo = a > b ? a - b : b - a, hi = (a + b < 3) ? a + b : 3;
                for (int c = lo; c <= hi; c++) {
                    l1[p] = a; l2[p] = b; l3[p] = c;
                    cgo[p] = cg; zo[p] = z; rk[p] = rank[c]++;
                    cg += (2 * a + 1) * (2 * b + 1) * (2 * c + 1);
                    z  += (2 * a + 1) * (2 * c + 1);
                    p++;
                }
            }
    }
};
constexpr Tables TB;
constexpr int    XB_[4] = {0, 64, 256, 576};
constexpr int    FI_[4] = {256, 576, 704, 640};
constexpr size_t MB_[4] = {0ull, 524288ull, 4063232ull, 11272192ull};

__device__ float g_CG[NCG];
__device__ int2  g_ZM[NZ];                       // x=cg base, y=ybase|(d3<<8)|(d2<<16)
__device__ float g_Z[(size_t)E_EDGES * ZPAD];    // per-edge z (pad zero-init .bss)
__device__ float g_M[M_TOTAL];                   // scattered messages [l3][n][m][cc]

// ---------------- z precompute: one CTA per edge ----------------
__global__ __launch_bounds__(256)
void z_kernel(const float* __restrict__ y0, const float* __restrict__ y1,
              const float* __restrict__ y2, const float* __restrict__ y3)
{
    __shared__ float ysh[16];
    const int e = blockIdx.x, tid = threadIdx.x;
    if (tid < 16) {
        float v;
        if (tid == 0)      v = y0[e];
        else if (tid < 4)  v = y1[e * 3 + (tid - 1)];
        else if (tid < 9)  v = y2[e * 5 + (tid - 4)];
        else               v = y3[e * 7 + (tid - 9)];
        ysh[tid] = v;
    }
    __syncthreads();
    float* zr = g_Z + (size_t)e * ZPAD;
    #pragma unroll
    for (int j0 = 0; j0 < 3; j0++) {
        int j = tid + j0 * 256;
        if (j < NZ) {
            int2 m = g_ZM[j];
            int yb = m.y & 0xff, st = (m.y >> 8) & 0xff, nm = (m.y >> 16) & 0xff;
            float s = 0.f;
            for (int q = 0; q < nm; q++) s += g_CG[m.x + q * st] * ysh[yb + q];
            zr[j] = s;
        }
    }
}

// ---------------- per-path device helpers (all constants compile-time) ----------------
template<int P>
__device__ __forceinline__ void path_compute(const float* __restrict__ xs,
                                             const float* __restrict__ zs,
                                             float w, float* acc, int c)
{
    constexpr int D1 = 2 * TB.l1[P] + 1;
    constexpr int D3 = 2 * TB.l3[P] + 1;
    constexpr int ZO = TB.zo[P];
    constexpr int XB = XB_[TB.l1[P]];
    float xv[D1];
    #pragma unroll
    for (int l = 0; l < D1; l++) xv[l] = xs[XB + c * D1 + l];
    #pragma unroll
    for (int n = 0; n < D3; n++) {
        float t = 0.f;
        #pragma unroll
        for (int l = 0; l < D1; l++) t += xv[l] * zs[ZO + l * D3 + n];
        acc[n] += w * t;
    }
}

template<int P>
__device__ __forceinline__ void path_store(int node, int c, const float* acc)
{
    constexpr int L3 = TB.l3[P];
    constexpr int D3 = 2 * L3 + 1;
    constexpr int FI = FI_[L3];
    float* p = g_M + MB_[L3] + (size_t)node * (D3 * FI) + TB.rk[P] * 64 + c;
    #pragma unroll
    for (int n = 0; n < D3; n++) p[(size_t)n * FI] = acc[n];
}

// balanced path groups (Sum d1*d3 = 184/184/186/184); (path, acc-offset, w-slot)
#define G0(OP) OP(33,0,0) OP(16,7,1) OP(28,14,2) OP(10,19,3) OP(7,26,4) OP(11,31,5) OP(4,36,6) OP(2,39,7)
#define G1(OP) OP(24,0,0) OP(20,7,1) OP(32,14,2) OP(12,19,3) OP(9,26,4) OP(14,31,5) OP(6,34,6) OP(17,37,7)
#define G2(OP) OP(26,0,0) OP(23,7,1) OP(13,14,2) OP(19,19,3) OP(27,24,4) OP(18,27,5) OP(8,30,6) OP(1,33,7) OP(5,36,8) OP(0,37,9)
#define G3(OP) OP(29,0,0) OP(25,7,1) OP(15,12,2) OP(22,17,3) OP(31,22,4) OP(21,25,5) OP(3,28,6) OP(30,35,7)
#define FORG(OP) if (g == 0) { G0(OP) } else if (g == 1) { G1(OP) } else if (g == 2) { G2(OP) } else { G3(OP) }

#define OPW(P,A,I) wdst[I] = __ldg(wrow + P * 64);
#define OPC(P,A,I) path_compute<P>(xs, zs, wreg[I], acc + A, c);
#define OPS(P,A,I) path_store<P>(node, c, acc + A);

// ---------------- edge + scatter kernel: one CTA per destination node ----------------
__global__ __launch_bounds__(256)
void edge_kernel(const float* __restrict__ x0, const float* __restrict__ x1,
                 const float* __restrict__ x2, const float* __restrict__ x3,
                 const float* __restrict__ ws, const int* __restrict__ eidx)
{
    __shared__ __align__(16) float xsb[2][1024];
    __shared__ __align__(16) float zsb[2][ZPAD];
    __shared__ int elist[ECAP];
    __shared__ int scanb[256];
    __shared__ int s_ne;

    const int node = blockIdx.x;
    const int tid  = threadIdx.x;
    const int* srcA = eidx;
    const int* dstA = eidx + E_EDGES;

    // ---- deterministic compaction of in-edges ----
    int cnt = 0;
    #pragma unroll
    for (int j = 0; j < E_EDGES / 256; j++)
        cnt += (dstA[tid + j * 256] == node) ? 1 : 0;
    scanb[tid] = cnt;
    __syncthreads();
    for (int off = 1; off < 256; off <<= 1) {
        int v = (tid >= off) ? scanb[tid - off] : 0;
        __syncthreads();
        scanb[tid] += v;
        __syncthreads();
    }
    int pos = scanb[tid] - cnt;
    if (tid == 255) s_ne = (scanb[255] < ECAP) ? scanb[255] : ECAP;
    __syncthreads();
    #pragma unroll
    for (int j = 0; j < E_EDGES / 256; j++) {
        int e = tid + j * 256;
        if (dstA[e] == node) { if (pos < ECAP) elist[pos] = e; pos++; }
    }
    __syncthreads();
    const int ne = s_ne;

    const int g = tid >> 6;
    const int c = tid & 63;

    float acc[44];
    #pragma unroll
    for (int i = 0; i < 44; i++) acc[i] = 0.f;
    float wreg[10], wnx[10];
    float4 xr = make_float4(0, 0, 0, 0), zr = make_float4(0, 0, 0, 0);

    auto ldx = [&](int s) -> float4 {
        int i4 = tid * 4;
        if (tid < 16)   return *(const float4*)(x0 + s * 64  + i4);
        if (tid < 64)   return *(const float4*)(x1 + s * 192 + (i4 - 64));
        if (tid < 144)  return *(const float4*)(x2 + s * 320 + (i4 - 256));
        return                 *(const float4*)(x3 + s * 448 + (i4 - 576));
    };

    // prologue: prefetch edge 0 into registers
    if (ne > 0) {
        int e0 = elist[0];
        int s0 = srcA[e0];
        xr = ldx(s0);
        if (tid < ZPAD / 4) zr = *(const float4*)(g_Z + (size_t)e0 * ZPAD + tid * 4);
        const float* wrow = ws + (size_t)e0 * WS_STRIDE + c;
        float* wdst = wreg;
        FORG(OPW)
    }

    for (int k = 0; k < ne; k++) {
        const int b = k & 1;
        // commit staged registers to smem buffer b
        *(float4*)&xsb[b][tid * 4] = xr;
        if (tid < ZPAD / 4) *(float4*)&zsb[b][tid * 4] = zr;
        __syncthreads();

        // prefetch edge k+1 (latency overlapped with compute below)
        if (k + 1 < ne) {
            int e1 = elist[k + 1];
            int s1 = srcA[e1];
            xr = ldx(s1);
            if (tid < ZPAD / 4) zr = *(const float4*)(g_Z + (size_t)e1 * ZPAD + tid * 4);
            const float* wrow = ws + (size_t)e1 * WS_STRIDE + c;
            float* wdst = wnx;
            FORG(OPW)
        }

        // compute on buffer b (register accumulators)
        const float* xs = xsb[b];
        const float* zs = zsb[b];
        FORG(OPC)

        #pragma unroll
        for (int i = 0; i < 10; i++) wreg[i] = wnx[i];
    }

    // epilogue: write register accumulators straight to g_M (coalesced in c)
    FORG(OPS)
}

// ---------------- output GEMM kernel (unchanged from passing R9) ----------------
__global__ __launch_bounds__(256)
void gemm_kernel(const float* __restrict__ W0, const float* __restrict__ W1,
                 const float* __restrict__ W2, const float* __restrict__ W3,
                 float* __restrict__ out)
{
    __shared__ float As[32][68];
    __shared__ float Bs[32][64];

    const int blk = blockIdx.x, tid = threadIdx.x;
    int l3, t0;
    if (blk < 32)       { l3 = 0; t0 = 0; }
    else if (blk < 128) { l3 = 1; t0 = 32; }
    else if (blk < 288) { l3 = 2; t0 = 128; }
    else                { l3 = 3; t0 = 288; }
    const int rowTile = blk - t0;

    const int  KA[4] = {256, 576, 704, 640};
    const long MB[4] = {0L, 524288L, 4063232L, 11272192L};
    const long OB[4] = {0L, 131072L, 524288L, 1179648L};
    const int  K  = KA[l3];
    const int  ld = 2 * l3 + 1;
    const float* A = g_M + MB[l3] + (long)rowTile * 64 * K;
    const float* B = (l3 == 0) ? W0 : (l3 == 1) ? W1 : (l3 == 2) ? W2 : W3;
    float* Ob = out + OB[l3];

    const int tr = (tid >> 4) << 2, tc = (tid & 15) << 2;
    const int arow = tid >> 2, ac0 = (tid & 3) << 3;
    const int brow = tid >> 3, bc0 = (tid & 7) << 3;

    float ac[4][4] = {};

    for (int k0 = 0; k0 < K; k0 += 32) {
        float4 a0 = *(const float4*)(A + (long)arow * K + k0 + ac0);
        float4 a1 = *(const float4*)(A + (long)arow * K + k0 + ac0 + 4);
        As[ac0 + 0][arow] = a0.x; As[ac0 + 1][arow] = a0.y;
        As[ac0 + 2][arow] = a0.z; As[ac0 + 3][arow] = a0.w;
        As[ac0 + 4][arow] = a1.x; As[ac0 + 5][arow] = a1.y;
        As[ac0 + 6][arow] = a1.z; As[ac0 + 7][arow] = a1.w;
        *(float4*)&Bs[brow][bc0]     = *(const float4*)(B + (long)(k0 + brow) * 64 + bc0);
        *(float4*)&Bs[brow][bc0 + 4] = *(const float4*)(B + (long)(k0 + brow) * 64 + bc0 + 4);
        __syncthreads();
        #pragma unroll
        for (int k = 0; k < 32; k++) {
            float4 av = *(const float4*)&As[k][tr];
            float4 bv = *(const float4*)&Bs[k][tc];
            ac[0][0] += av.x * bv.x; ac[0][1] += av.x * bv.y;
            ac[0][2] += av.x * bv.z; ac[0][3] += av.x * bv.w;
            ac[1][0] += av.y * bv.x; ac[1][1] += av.y * bv.y;
            ac[1][2] += av.y * bv.z; ac[1][3] += av.y * bv.w;
            ac[2][0] += av.z * bv.x; ac[2][1] += av.z * bv.y;
            ac[2][2] += av.z * bv.z; ac[2][3] += av.z * bv.w;
            ac[3][0] += av.w * bv.x; ac[3][1] += av.w * bv.y;
            ac[3][2] += av.w * bv.z; ac[3][3] += av.w * bv.w;
        }
        __syncthreads();
    }

    #pragma unroll
    for (int i = 0; i < 4; i++) {
        int r = rowTile * 64 + tr + i;
        int n = r / ld, m = r - n * ld;
        float* op = Ob + (long)n * 64 * ld + m;
        #pragma unroll
        for (int j = 0; j < 4; j++) op[(long)(tc + j) * ld] = ac[i][j];
    }
}

// ---------------- host: regenerate numpy CG constants + z metadata ----------------
static void build_host_tables(float* cg, int2* zm)
{
    uint32_t mt[624]; int mti;
    uint32_t sd = 1234u;
    for (int i = 0; i < 624; i++) {
        mt[i] = sd;
        sd = 1812433253u * (sd ^ (sd >> 30)) + (uint32_t)i + 1u;
    }
    mti = 624;
    auto mt_next = [&]() -> uint32_t {
        if (mti >= 624) {
            for (int i = 0; i < 624; i++) {
                uint32_t y = (mt[i] & 0x80000000u) | (mt[(i + 1) % 624] & 0x7fffffffu);
                mt[i] = mt[(i + 397) % 624] ^ (y >> 1) ^ ((y & 1u) ? 0x9908b0dfu : 0u);
            }
            mti = 0;
        }
        uint32_t y = mt[mti++];
        y ^= y >> 11; y ^= (y << 7) & 0x9d2c5680u;
        y ^= (y << 15) & 0xefc60000u; y ^= y >> 18;
        return y;
    };
    auto rk_double = [&]() -> double {
        uint32_t a = mt_next() >> 5, b = mt_next() >> 6;
        return ((double)a * 67108864.0 + (double)b) / 9007199254740992.0;
    };
    bool has_g = false; double gch = 0.0;
    auto gauss = [&]() -> double {
        if (has_g) { has_g = false; return gch; }
        double x1, x2, r2;
        do {
            x1 = 2.0 * rk_double() - 1.0;
            x2 = 2.0 * rk_double() - 1.0;
            r2 = x1 * x1 + x2 * x2;
        } while (r2 >= 1.0 || r2 == 0.0);
        double f = sqrt(-2.0 * log(r2) / r2);
        gch = f * x1; has_g = true;
        return f * x2;
    };

    const int ybase[4] = {0, 1, 4, 9};
    int p = 0, cgoff = 0, zoff = 0;
    for (int a = 0; a < 4; a++)
        for (int b = 0; b < 4; b++) {
            int lo = a > b ? a - b : b - a, hi = (a + b < 3) ? a + b : 3;
            for (int c = lo; c <= hi; c++) {
                int d1 = 2 * a + 1, d2 = 2 * b + 1, d3 = 2 * c + 1;
                int n = d1 * d2 * d3;
                for (int t = 0; t < n; t++) cg[cgoff + t] = (float)(gauss() * 0.2);
                for (int l = 0; l < d1; l++)
                    for (int nn = 0; nn < d3; nn++) {
                        zm[zoff + l * d3 + nn].x = cgoff + l * d2 * d3 + nn;
                        zm[zoff + l * d3 + nn].y = ybase[b] | (d3 << 8) | (d2 << 16);
                    }
                cgoff += n; zoff += d1 * d3; p++;
            }
        }
}

extern "C" void kernel_launch(void* const* d_in, const int* in_sizes, int n_in,
                              void* d_out, int out_size)
{
    static float h_cg[NCG];
    static int2  h_zm[NZ];
    build_host_tables(h_cg, h_zm);

    cudaMemcpyToSymbolAsync(g_CG, h_cg, sizeof(h_cg), 0, cudaMemcpyHostToDevice, 0);
    cudaMemcpyToSymbolAsync(g_ZM, h_zm, sizeof(h_zm), 0, cudaMemcpyHostToDevice, 0);

    const float *x[4], *y[4], *wl[4], *wsP;
    const int* ei;
    if (n_in >= 14 && in_sizes[1] == E_EDGES) {
        for (int l = 0; l < 4; l++) {
            x[l]  = (const float*)d_in[3 * l + 0];
            y[l]  = (const float*)d_in[3 * l + 1];
            wl[l] = (const float*)d_in[3 * l + 2];
        }
        wsP = (const float*)d_in[12];
        ei  = (const int*)d_in[13];
    } else {
        for (int l = 0; l < 4; l++) {
            x[l]  = (const float*)d_in[l];
            y[l]  = (const float*)d_in[4 + l];
            wl[l] = (const float*)d_in[9 + l];
        }
        wsP = (const float*)d_in[8];
        ei  = (const int*)d_in[13];
    }

    z_kernel<<<E_EDGES, 256>>>(y[0], y[1], y[2], y[3]);
    edge_kernel<<<N_NODES, 256>>>(x[0], x[1], x[2], x[3], wsP, ei);
    gemm_kernel<<<512, 256>>>(wl[0], wl[1], wl[2], wl[3], (float*)d_out);
    (void)out_size;
}

// round 16
// speedup vs baseline: 1.4691x; 1.1082x over previous
#include <cuda_runtime.h>
#include <cuda_bf16.h>
#include <cstdint>
#include <cmath>
#include <cstring>

// ---------------- problem constants ----------------
#define N_NODES   2048
#define E_EDGES   8192
#define NPATH     34
#define NZ        738
#define NCG       3436
#define WS_STRIDE 2176
#define ECAP      256
#define ZPADN     1040      // padded per-edge z row (1028 used), 16-float multiple
#define M_TOTAL   20447232

typedef unsigned long long ull;

// ---------------- compile-time path tables ----------------
struct Tables {
    int l1[NPATH], l2[NPATH], l3[NPATH], cgo[NPATH], zo[NPATH], zpo[NPATH], rk[NPATH];
    int zpend;
    constexpr Tables() : l1(), l2(), l3(), cgo(), zo(), zpo(), rk(), zpend(0) {
        int p = 0, cg = 0, z = 0, zp = 0; int rank[4] = {0, 0, 0, 0};
        for (int a = 0; a < 4; a++)
            for (int b = 0; b < 4; b++) {
                int lo = a > b ? a - b : b - a, hi = (a + b < 3) ? a + b : 3;
                for (int c = lo; c <= hi; c++) {
                    int d1 = 2 * a + 1, d3 = 2 * c + 1;
                    int pitch = (d3 <= 3) ? 4 : 8;
                    l1[p] = a; l2[p] = b; l3[p] = c;
                    cgo[p] = cg; zo[p] = z; zpo[p] = zp; rk[p] = rank[c]++;
                    cg += d1 * (2 * b + 1) * d3;
                    z  += d1 * d3;
                    zp += d1 * pitch;
                    p++;
                }
            }
        zpend = zp;
    }
};
constexpr Tables TB;
static_assert(TB.zpend == 1028, "padded z size");
constexpr int    XB_[4] = {0, 64, 256, 576};
constexpr int    FI_[4] = {256, 576, 704, 640};
constexpr size_t MB_[4] = {0ull, 524288ull, 4063232ull, 11272192ull};

__device__ float g_CG[NCG];
__device__ int4  g_ZM[NZ];                        // x=cg base, y=yb|(d3<<8)|(d2<<16), z=padded off
__device__ float g_Z[(size_t)E_EDGES * ZPADN];    // per-edge z, padded (pads stay zero)
__device__ float g_M[M_TOTAL];                    // scattered messages [l3][n][m][cc]

// ---------------- f32x2 helpers ----------------
__device__ __forceinline__ ull pk2(float f) {
    ull d; asm("mov.b64 %0, {%1, %1};" : "=l"(d) : "r"(__float_as_uint(f)));
    return d;
}
__device__ __forceinline__ ull pkpair(float a, float b) {
    ull d; asm("mov.b64 %0, {%1, %2};" : "=l"(d)
               : "r"(__float_as_uint(a)), "r"(__float_as_uint(b)));
    return d;
}
__device__ __forceinline__ void ffma2(ull& d, ull a, ull b, ull c) {
    asm("fma.rn.f32x2 %0, %1, %2, %3;" : "=l"(d) : "l"(a), "l"(b), "l"(c));
}
__device__ __forceinline__ float lo2(ull v) { return __uint_as_float((unsigned)v); }
__device__ __forceinline__ float hi2(ull v) { return __uint_as_float((unsigned)(v >> 32)); }

// ---------------- z precompute: 512 CTAs x 16 edges ----------------
__global__ __launch_bounds__(256)
void z_kernel(const float* __restrict__ y0, const float* __restrict__ y1,
              const float* __restrict__ y2, const float* __restrict__ y3)
{
    __shared__ float ysh[16][16];
    const int e0 = blockIdx.x * 16, tid = threadIdx.x;
    {
        int ee = tid >> 4, ii = tid & 15, e = e0 + ee;
        float v;
        if (ii == 0)      v = y0[e];
        else if (ii < 4)  v = y1[e * 3 + (ii - 1)];
        else if (ii < 9)  v = y2[e * 5 + (ii - 4)];
        else              v = y3[e * 7 + (ii - 9)];
        ysh[ee][ii] = v;
    }
    __syncthreads();
    #pragma unroll
    for (int r = 0; r < 3; r++) {
        int j = tid + r * 256;
        if (j < NZ) {
            int4 m = g_ZM[j];
            int yb = m.y & 0xff, st = (m.y >> 8) & 0xff, nm = (m.y >> 16) & 0xff;
            float cgr[7];
            #pragma unroll
            for (int q = 0; q < 7; q++)
                cgr[q] = (q < nm) ? g_CG[m.x + q * st] : 0.f;
            float* zp = g_Z + (size_t)e0 * ZPADN + m.z;
            #pragma unroll
            for (int e = 0; e < 16; e++) {
                float s = 0.f;
                #pragma unroll
                for (int q = 0; q < 7; q++) s += cgr[q] * ysh[e][yb + q];
                zp[(size_t)e * ZPADN] = s;
            }
        }
    }
}

// ---------------- per-path device helpers ----------------
template<int P>
__device__ __forceinline__ void path_compute(const float* __restrict__ xs,
                                             const float* __restrict__ zs,
                                             float w, float* acc, int c)
{
    constexpr int D1 = 2 * TB.l1[P] + 1;
    constexpr int D3 = 2 * TB.l3[P] + 1;
    constexpr int PITCH = (D3 <= 3) ? 4 : 8;
    constexpr int ZPO = TB.zpo[P];
    constexpr int XB = XB_[TB.l1[P]];
    constexpr int NT = (D3 + 1) / 2;
    ull t[NT];
    #pragma unroll
    for (int i = 0; i < NT; i++) t[i] = 0ull;
    #pragma unroll
    for (int l = 0; l < D1; l++) {
        ull xv = pk2(xs[XB + l * 64 + c]);           // conflict-free (lane = c)
        float4 za = *(const float4*)(zs + ZPO + l * PITCH);   // warp broadcast
        ffma2(t[0], xv, pkpair(za.x, za.y), t[0]);
        if constexpr (D3 > 2) ffma2(t[1], xv, pkpair(za.z, za.w), t[1]);
        if constexpr (PITCH == 8) {
            float4 zb = *(const float4*)(zs + ZPO + l * PITCH + 4);
            ffma2(t[2], xv, pkpair(zb.x, zb.y), t[2]);
            if constexpr (D3 > 6) ffma2(t[3], xv, pkpair(zb.z, zb.w), t[3]);
        }
    }
    #pragma unroll
    for (int n = 0; n < D3; n++)
        acc[n] += w * ((n & 1) ? hi2(t[n / 2]) : lo2(t[n / 2]));
}

template<int P>
__device__ __forceinline__ void path_store(int node, int c, const float* acc)
{
    constexpr int L3 = TB.l3[P];
    constexpr int D3 = 2 * L3 + 1;
    constexpr int FI = FI_[L3];
    constexpr size_t MBASE = MB_[L3];     // constant-expression use only
    constexpr int RK = TB.rk[P];
    float* p = g_M + MBASE + (size_t)node * (D3 * FI) + RK * 64 + c;
    #pragma unroll
    for (int n = 0; n < D3; n++) p[(size_t)n * FI] = acc[n];
}

// balanced path groups; (path, acc-offset, w-slot) -- validated in R12
#define G0(OP) OP(33,0,0) OP(16,7,1) OP(28,14,2) OP(10,19,3) OP(7,26,4) OP(11,31,5) OP(4,36,6) OP(2,39,7)
#define G1(OP) OP(24,0,0) OP(20,7,1) OP(32,14,2) OP(12,19,3) OP(9,26,4) OP(14,31,5) OP(6,34,6) OP(17,37,7)
#define G2(OP) OP(26,0,0) OP(23,7,1) OP(13,14,2) OP(19,19,3) OP(27,24,4) OP(18,27,5) OP(8,30,6) OP(1,33,7) OP(5,36,8) OP(0,37,9)
#define G3(OP) OP(29,0,0) OP(25,7,1) OP(15,12,2) OP(22,17,3) OP(31,22,4) OP(21,25,5) OP(3,28,6) OP(30,35,7)
#define FORG(OP) if (g == 0) { G0(OP) } else if (g == 1) { G1(OP) } else if (g == 2) { G2(OP) } else { G3(OP) }

#define OPW(P,A,I) wdst[I] = __ldg(wrow + P * 64);
#define OPC(P,A,I) path_compute<P>(xs, zs, wreg[I], acc + A, c);
#define OPS(P,A,I) path_store<P>(node, c, acc + A);

// ---------------- edge + scatter kernel: one CTA per destination node ----------------
__global__ __launch_bounds__(256)
void edge_kernel(const float* __restrict__ x0, const float* __restrict__ x1,
                 const float* __restrict__ x2, const float* __restrict__ x3,
                 const float* __restrict__ ws, const int* __restrict__ eidx)
{
    __shared__ __align__(16) float xsb[2][1024];   // transposed: [l*64 + c] per degree block
    __shared__ __align__(16) float zsb[2][ZPADN];
    __shared__ int elist[ECAP];
    __shared__ int scanb[256];
    __shared__ int s_ne;

    const int node = blockIdx.x;
    const int tid  = threadIdx.x;
    const int* srcA = eidx;
    const int* dstA = eidx + E_EDGES;

    // ---- deterministic compaction of in-edges ----
    int cnt = 0;
    #pragma unroll
    for (int j = 0; j < E_EDGES / 256; j++)
        cnt += (dstA[tid + j * 256] == node) ? 1 : 0;
    scanb[tid] = cnt;
    __syncthreads();
    for (int off = 1; off < 256; off <<= 1) {
        int v = (tid >= off) ? scanb[tid - off] : 0;
        __syncthreads();
        scanb[tid] += v;
        __syncthreads();
    }
    int pos = scanb[tid] - cnt;
    if (tid == 255) s_ne = (scanb[255] < ECAP) ? scanb[255] : ECAP;
    __syncthreads();
    #pragma unroll
    for (int j = 0; j < E_EDGES / 256; j++) {
        int e = tid + j * 256;
        if (dstA[e] == node) { if (pos < ECAP) elist[pos] = e; pos++; }
    }
    __syncthreads();
    const int ne = s_ne;

    const int g = tid >> 6;
    const int c = tid & 63;

    float acc[44];
    #pragma unroll
    for (int i = 0; i < 44; i++) acc[i] = 0.f;
    float wreg[10], wnx[10];
    float4 xr = make_float4(0, 0, 0, 0);
    float4 zr = make_float4(0, 0, 0, 0), zr2 = make_float4(0, 0, 0, 0);

    auto ldx = [&](int s) -> float4 {
        int i4 = tid * 4;
        if (tid < 16)   return *(const float4*)(x0 + s * 64  + i4);
        if (tid < 64)   return *(const float4*)(x1 + s * 192 + (i4 - 64));
        if (tid < 144)  return *(const float4*)(x2 + s * 320 + (i4 - 256));
        return                 *(const float4*)(x3 + s * 448 + (i4 - 576));
    };
    auto ldz = [&](int e) {
        const float* zrow = g_Z + (size_t)e * ZPADN;
        zr = *(const float4*)(zrow + tid * 4);
        if (tid < 4) zr2 = *(const float4*)(zrow + 1024 + tid * 4);
    };
    auto commit = [&](int b) {
        // transpose x into [l][c] blocks while committing
        float v[4] = {xr.x, xr.y, xr.z, xr.w};
        if (tid < 16) {
            *(float4*)&xsb[b][tid * 4] = xr;                       // D1=1: identity
        } else if (tid < 64) {
            int idx = tid * 4 - 64;
            #pragma unroll
            for (int j = 0; j < 4; j++) {
                int id = idx + j;
                xsb[b][64 + (id % 3) * 64 + id / 3] = v[j];
            }
        } else if (tid < 144) {
            int idx = tid * 4 - 256;
            #pragma unroll
            for (int j = 0; j < 4; j++) {
                int id = idx + j;
                xsb[b][256 + (id % 5) * 64 + id / 5] = v[j];
            }
        } else {
            int idx = tid * 4 - 576;
            #pragma unroll
            for (int j = 0; j < 4; j++) {
                int id = idx + j;
                xsb[b][576 + (id % 7) * 64 + id / 7] = v[j];
            }
        }
        *(float4*)&zsb[b][tid * 4] = zr;
        if (tid < 4) *(float4*)&zsb[b][1024 + tid * 4] = zr2;
    };

    // prologue: prefetch edge 0
    if (ne > 0) {
        int e0 = elist[0];
        xr = ldx(srcA[e0]);
        ldz(e0);
        const float* wrow = ws + (size_t)e0 * WS_STRIDE + c;
        float* wdst = wreg;
        FORG(OPW)
    }

    for (int k = 0; k < ne; k++) {
        const int b = k & 1;
        commit(b);
        __syncthreads();

        if (k + 1 < ne) {                      // prefetch next edge under compute
            int e1 = elist[k + 1];
            xr = ldx(srcA[e1]);
            ldz(e1);
            const float* wrow = ws + (size_t)e1 * WS_STRIDE + c;
            float* wdst = wnx;
            FORG(OPW)
        }

        const float* xs = xsb[b];
        const float* zs = zsb[b];
        FORG(OPC)

        #pragma unroll
        for (int i = 0; i < 10; i++) wreg[i] = wnx[i];
    }

    FORG(OPS)
}

// ---------------- output GEMM: BM=128 BN=64 BK=16, 8x4/thread, f32x2, dbuf ----------------
__global__ __launch_bounds__(256)
void gemm_kernel(const float* __restrict__ W0, const float* __restrict__ W1,
                 const float* __restrict__ W2, const float* __restrict__ W3,
                 float* __restrict__ out)
{
    __shared__ float As[2][16][136];   // transposed A tile, 136 keeps 16B alignment
    __shared__ float Bs[2][16][64];

    const int blk = blockIdx.x, tid = threadIdx.x;
    int l3, t0;
    if (blk < 16)       { l3 = 0; t0 = 0; }
    else if (blk < 64)  { l3 = 1; t0 = 16; }
    else if (blk < 144) { l3 = 2; t0 = 64; }
    else                { l3 = 3; t0 = 144; }
    const int rowTile = blk - t0;

    const int  KA[4]  = {256, 576, 704, 640};
    const long MBl[4] = {0L, 524288L, 4063232L, 11272192L};   // device-local copy
    const long OB[4]  = {0L, 131072L, 524288L, 1179648L};
    const int  K  = KA[l3];
    const int  ld = 2 * l3 + 1;
    const float* A = g_M + MBl[l3] + (long)rowTile * 128 * K;
    const float* B = (l3 == 0) ? W0 : (l3 == 1) ? W1 : (l3 == 2) ? W2 : W3;
    float* Ob = out + OB[l3];

    const int arow = tid >> 1, ac0 = (tid & 1) * 8;
    const int brow = tid >> 4, bc0 = (tid & 15) * 4;
    const int tr = (tid >> 4) * 8, tc = (tid & 15) * 4;

    ull acc2[8][2];
    #pragma unroll
    for (int i = 0; i < 8; i++) { acc2[i][0] = 0ull; acc2[i][1] = 0ull; }

    float4 a0, a1, b0;
    auto ldtile = [&](int k0) {
        a0 = *(const float4*)(A + (long)arow * K + k0 + ac0);
        a1 = *(const float4*)(A + (long)arow * K + k0 + ac0 + 4);
        b0 = *(const float4*)(B + (long)(k0 + brow) * 64 + bc0);
    };
    ldtile(0);

    const int nt = K / 16;
    for (int t = 0; t < nt; t++) {
        const int b = t & 1;
        As[b][ac0 + 0][arow] = a0.x; As[b][ac0 + 1][arow] = a0.y;
        As[b][ac0 + 2][arow] = a0.z; As[b][ac0 + 3][arow] = a0.w;
        As[b][ac0 + 4][arow] = a1.x; As[b][ac0 + 5][arow] = a1.y;
        As[b][ac0 + 6][arow] = a1.z; As[b][ac0 + 7][arow] = a1.w;
        *(float4*)&Bs[b][brow][bc0] = b0;
        __syncthreads();

        if (t + 1 < nt) ldtile((t + 1) * 16);

        #pragma unroll
        for (int kk = 0; kk < 16; kk++) {
            float4 av0 = *(const float4*)&As[b][kk][tr];
            float4 av1 = *(const float4*)&As[b][kk][tr + 4];
            float4 bv  = *(const float4*)&Bs[b][kk][tc];
            ull bw0 = pkpair(bv.x, bv.y), bw1 = pkpair(bv.z, bv.w);
            float av[8] = {av0.x, av0.y, av0.z, av0.w, av1.x, av1.y, av1.z, av1.w};
            #pragma unroll
            for (int i = 0; i < 8; i++) {
                ull ad = pk2(av[i]);
                ffma2(acc2[i][0], ad, bw0, acc2[i][0]);
                ffma2(acc2[i][1], ad, bw1, acc2[i][1]);
            }
        }
        // single sync per tile: writers of buf b^1 (next iter) are separated from
        // its previous readers (iter t-1) by this barrier
        __syncthreads();
    }

    #pragma unroll
    for (int i = 0; i < 8; i++) {
        int r = rowTile * 128 + tr + i;
        int n = r / ld, m = r - n * ld;
        float* op = Ob + (long)n * 64 * ld + m;
        op[(long)(tc + 0) * ld] = lo2(acc2[i][0]);
        op[(long)(tc + 1) * ld] = hi2(acc2[i][0]);
        op[(long)(tc + 2) * ld] = lo2(acc2[i][1]);
        op[(long)(tc + 3) * ld] = hi2(acc2[i][1]);
    }
}

// ---------------- host: regenerate numpy CG constants + z metadata ----------------
static void build_host_tables(float* cg, int4* zm)
{
    uint32_t mt[624]; int mti;
    uint32_t sd = 1234u;
    for (int i = 0; i < 624; i++) {
        mt[i] = sd;
        sd = 1812433253u * (sd ^ (sd >> 30)) + (uint32_t)i + 1u;
    }
    mti = 624;
    auto mt_next = [&]() -> uint32_t {
        if (mti >= 624) {
            for (int i = 0; i < 624; i++) {
                uint32_t y = (mt[i] & 0x80000000u) | (mt[(i + 1) % 624] & 0x7fffffffu);
                mt[i] = mt[(i + 397) % 624] ^ (y >> 1) ^ ((y & 1u) ? 0x9908b0dfu : 0u);
            }
            mti = 0;
        }
        uint32_t y = mt[mti++];
        y ^= y >> 11; y ^= (y << 7) & 0x9d2c5680u;
        y ^= (y << 15) & 0xefc60000u; y ^= y >> 18;
        return y;
    };
    auto rk_double = [&]() -> double {
        uint32_t a = mt_next() >> 5, b = mt_next() >> 6;
        return ((double)a * 67108864.0 + (double)b) / 9007199254740992.0;
    };
    bool has_g = false; double gch = 0.0;
    auto gauss = [&]() -> double {
        if (has_g) { has_g = false; return gch; }
        double x1, x2, r2;
        do {
            x1 = 2.0 * rk_double() - 1.0;
            x2 = 2.0 * rk_double() - 1.0;
            r2 = x1 * x1 + x2 * x2;
        } while (r2 >= 1.0 || r2 == 0.0);
        double f = sqrt(-2.0 * log(r2) / r2);
        gch = f * x1; has_g = true;
        return f * x2;
    };

    const int ybase[4] = {0, 1, 4, 9};
    int cgoff = 0, zoff = 0, zpoff = 0;
    for (int a = 0; a < 4; a++)
        for (int b = 0; b < 4; b++) {
            int lo = a > b ? a - b : b - a, hi = (a + b < 3) ? a + b : 3;
            for (int c = lo; c <= hi; c++) {
                int d1 = 2 * a + 1, d2 = 2 * b + 1, d3 = 2 * c + 1;
                int pitch = (d3 <= 3) ? 4 : 8;
                int n = d1 * d2 * d3;
                for (int t = 0; t < n; t++) cg[cgoff + t] = (float)(gauss() * 0.2);
                for (int l = 0; l < d1; l++)
                    for (int nn = 0; nn < d3; nn++) {
                        int j = zoff + l * d3 + nn;
                        zm[j].x = cgoff + l * d2 * d3 + nn;
                        zm[j].y = ybase[b] | (d3 << 8) | (d2 << 16);
                        zm[j].z = zpoff + l * pitch + nn;
                        zm[j].w = 0;
                    }
                cgoff += n; zoff += d1 * d3; zpoff += d1 * pitch;
            }
        }
}

extern "C" void kernel_launch(void* const* d_in, const int* in_sizes, int n_in,
                              void* d_out, int out_size)
{
    static float h_cg[NCG];
    static int4  h_zm[NZ];
    build_host_tables(h_cg, h_zm);

    cudaMemcpyToSymbolAsync(g_CG, h_cg, sizeof(h_cg), 0, cudaMemcpyHostToDevice, 0);
    cudaMemcpyToSymbolAsync(g_ZM, h_zm, sizeof(h_zm), 0, cudaMemcpyHostToDevice, 0);

    const float *x[4], *y[4], *wl[4], *wsP;
    const int* ei;
    if (n_in >= 14 && in_sizes[1] == E_EDGES) {
        for (int l = 0; l < 4; l++) {
            x[l]  = (const float*)d_in[3 * l + 0];
            y[l]  = (const float*)d_in[3 * l + 1];
            wl[l] = (const float*)d_in[3 * l + 2];
        }
        wsP = (const float*)d_in[12];
        ei  = (const int*)d_in[13];
    } else {
        for (int l = 0; l < 4; l++) {
            x[l]  = (const float*)d_in[l];
            y[l]  = (const float*)d_in[4 + l];
            wl[l] = (const float*)d_in[9 + l];
        }
        wsP = (const float*)d_in[8];
        ei  = (const int*)d_in[13];
    }

    z_kernel<<<E_EDGES / 16, 256>>>(y[0], y[1], y[2], y[3]);
    edge_kernel<<<N_NODES, 256>>>(x[0], x[1], x[2], x[3], wsP, ei);
    gemm_kernel<<<256, 256>>>(wl[0], wl[1], wl[2], wl[3], (float*)d_out);
    (void)out_size;
}

// round 17
// speedup vs baseline: 1.6390x; 1.1157x over previous
#include <cuda_runtime.h>
#include <cuda_bf16.h>
#include <cstdint>
#include <cmath>
#include <cstring>

// ---------------- problem constants ----------------
#define N_NODES   2048
#define E_EDGES   8192
#define NPATH     34
#define NZ        738
#define NCG       3436
#define WS_STRIDE 2176
#define ECAP      256
#define ZPADN     1040      // padded per-edge z row (1028 used), 16-float multiple
#define M_TOTAL   20447232

typedef unsigned long long ull;

// ---------------- compile-time path tables ----------------
struct Tables {
    int l1[NPATH], l2[NPATH], l3[NPATH], cgo[NPATH], zo[NPATH], zpo[NPATH], rk[NPATH];
    int zpend;
    constexpr Tables() : l1(), l2(), l3(), cgo(), zo(), zpo(), rk(), zpend(0) {
        int p = 0, cg = 0, z = 0, zp = 0; int rank[4] = {0, 0, 0, 0};
        for (int a = 0; a < 4; a++)
            for (int b = 0; b < 4; b++) {
                int lo = a > b ? a - b : b - a, hi = (a + b < 3) ? a + b : 3;
                for (int c = lo; c <= hi; c++) {
                    int d1 = 2 * a + 1, d3 = 2 * c + 1;
                    int pitch = (d3 <= 3) ? 4 : 8;
                    l1[p] = a; l2[p] = b; l3[p] = c;
                    cgo[p] = cg; zo[p] = z; zpo[p] = zp; rk[p] = rank[c]++;
                    cg += d1 * (2 * b + 1) * d3;
                    z  += d1 * d3;
                    zp += d1 * pitch;
                    p++;
                }
            }
        zpend = zp;
    }
};
constexpr Tables TB;
static_assert(TB.zpend == 1028, "padded z size");
constexpr int    XB_[4] = {0, 64, 256, 576};
constexpr int    FI_[4] = {256, 576, 704, 640};
constexpr size_t MB_[4] = {0ull, 524288ull, 4063232ull, 11272192ull};

__device__ float g_CG[NCG];
__device__ int4  g_ZM[NZ];                        // x=cg base, y=yb|(d3<<8)|(d2<<16), z=padded off
__device__ float g_Z[(size_t)E_EDGES * ZPADN];    // per-edge z, padded (pads stay zero)
__device__ float g_M[M_TOTAL];                    // scattered messages [l3][n][m][cc]

// ---------------- f32x2 helpers (edge kernel) ----------------
__device__ __forceinline__ ull pk2(float f) {
    ull d; asm("mov.b64 %0, {%1, %1};" : "=l"(d) : "r"(__float_as_uint(f)));
    return d;
}
__device__ __forceinline__ ull pkpair(float a, float b) {
    ull d; asm("mov.b64 %0, {%1, %2};" : "=l"(d)
               : "r"(__float_as_uint(a)), "r"(__float_as_uint(b)));
    return d;
}
__device__ __forceinline__ void ffma2(ull& d, ull a, ull b, ull c) {
    asm("fma.rn.f32x2 %0, %1, %2, %3;" : "=l"(d) : "l"(a), "l"(b), "l"(c));
}
__device__ __forceinline__ float lo2(ull v) { return __uint_as_float((unsigned)v); }
__device__ __forceinline__ float hi2(ull v) { return __uint_as_float((unsigned)(v >> 32)); }

// ---------------- tf32 helpers (gemm) ----------------
__device__ __forceinline__ unsigned tf32cvt(float f) {
    unsigned u; asm("cvt.rna.tf32.f32 %0, %1;" : "=r"(u) : "f"(f));
    return u;
}
__device__ __forceinline__ void mma_tf32(float* c, unsigned a0, unsigned a1,
                                         unsigned a2, unsigned a3,
                                         unsigned b0, unsigned b1) {
    asm volatile(
        "mma.sync.aligned.m16n8k8.row.col.f32.tf32.tf32.f32 "
        "{%0,%1,%2,%3}, {%4,%5,%6,%7}, {%8,%9}, {%0,%1,%2,%3};"
        : "+f"(c[0]), "+f"(c[1]), "+f"(c[2]), "+f"(c[3])
        : "r"(a0), "r"(a1), "r"(a2), "r"(a3), "r"(b0), "r"(b1));
}

// ---------------- z precompute v2: warp-per-edge, coalesced stores ----------------
// grid 512 CTAs x 16 edges; warp w handles edges 2w, 2w+1; lanes sweep j.
__global__ __launch_bounds__(256)
void z_kernel(const float* __restrict__ y0, const float* __restrict__ y1,
              const float* __restrict__ y2, const float* __restrict__ y3)
{
    __shared__ float ysh[16][16];
    __shared__ float cgs[NCG];
    const int e0 = blockIdx.x * 16, tid = threadIdx.x;
    for (int i = tid; i < NCG; i += 256) cgs[i] = g_CG[i];
    {
        int ee = tid >> 4, ii = tid & 15, e = e0 + ee;
        float v;
        if (ii == 0)      v = y0[e];
        else if (ii < 4)  v = y1[e * 3 + (ii - 1)];
        else if (ii < 9)  v = y2[e * 5 + (ii - 4)];
        else              v = y3[e * 7 + (ii - 9)];
        ysh[ee][ii] = v;
    }
    __syncthreads();
    const int w = tid >> 5, lane = tid & 31;
    const int ea = 2 * w, eb = 2 * w + 1;
    float* za = g_Z + (size_t)(e0 + ea) * ZPADN;
    float* zb = g_Z + (size_t)(e0 + eb) * ZPADN;
    #pragma unroll 4
    for (int it = 0; it < (NZ + 31) / 32; it++) {
        int j = it * 32 + lane;
        if (j < NZ) {
            int4 m = g_ZM[j];
            int yb_ = m.y & 0xff, st = (m.y >> 8) & 0xff, nm = (m.y >> 16) & 0xff;
            float sa = 0.f, sb = 0.f;
            for (int q = 0; q < nm; q++) {
                float cg = cgs[m.x + q * st];
                sa += cg * ysh[ea][yb_ + q];
                sb += cg * ysh[eb][yb_ + q];
            }
            za[m.z] = sa;
            zb[m.z] = sb;
        }
    }
}

// ---------------- per-path device helpers (edge kernel) ----------------
template<int P>
__device__ __forceinline__ void path_compute(const float* __restrict__ xs,
                                             const float* __restrict__ zs,
                                             float w, float* acc, int c)
{
    constexpr int D1 = 2 * TB.l1[P] + 1;
    constexpr int D3 = 2 * TB.l3[P] + 1;
    constexpr int PITCH = (D3 <= 3) ? 4 : 8;
    constexpr int ZPO = TB.zpo[P];
    constexpr int XB = XB_[TB.l1[P]];
    constexpr int NT = (D3 + 1) / 2;
    ull t[NT];
    #pragma unroll
    for (int i = 0; i < NT; i++) t[i] = 0ull;
    #pragma unroll
    for (int l = 0; l < D1; l++) {
        ull xv = pk2(xs[XB + l * 64 + c]);           // conflict-free (lane = c)
        float4 za = *(const float4*)(zs + ZPO + l * PITCH);   // warp broadcast
        ffma2(t[0], xv, pkpair(za.x, za.y), t[0]);
        if constexpr (D3 > 2) ffma2(t[1], xv, pkpair(za.z, za.w), t[1]);
        if constexpr (PITCH == 8) {
            float4 zb = *(const float4*)(zs + ZPO + l * PITCH + 4);
            ffma2(t[2], xv, pkpair(zb.x, zb.y), t[2]);
            if constexpr (D3 > 6) ffma2(t[3], xv, pkpair(zb.z, zb.w), t[3]);
        }
    }
    #pragma unroll
    for (int n = 0; n < D3; n++)
        acc[n] += w * ((n & 1) ? hi2(t[n / 2]) : lo2(t[n / 2]));
}

template<int P>
__device__ __forceinline__ void path_store(int node, int c, const float* acc)
{
    constexpr int L3 = TB.l3[P];
    constexpr int D3 = 2 * L3 + 1;
    constexpr int FI = FI_[L3];
    constexpr size_t MBASE = MB_[L3];
    constexpr int RK = TB.rk[P];
    float* p = g_M + MBASE + (size_t)node * (D3 * FI) + RK * 64 + c;
    #pragma unroll
    for (int n = 0; n < D3; n++) p[(size_t)n * FI] = acc[n];
}

// balanced path groups; (path, acc-offset, w-slot) -- validated
#define G0(OP) OP(33,0,0) OP(16,7,1) OP(28,14,2) OP(10,19,3) OP(7,26,4) OP(11,31,5) OP(4,36,6) OP(2,39,7)
#define G1(OP) OP(24,0,0) OP(20,7,1) OP(32,14,2) OP(12,19,3) OP(9,26,4) OP(14,31,5) OP(6,34,6) OP(17,37,7)
#define G2(OP) OP(26,0,0) OP(23,7,1) OP(13,14,2) OP(19,19,3) OP(27,24,4) OP(18,27,5) OP(8,30,6) OP(1,33,7) OP(5,36,8) OP(0,37,9)
#define G3(OP) OP(29,0,0) OP(25,7,1) OP(15,12,2) OP(22,17,3) OP(31,22,4) OP(21,25,5) OP(3,28,6) OP(30,35,7)
#define FORG(OP) if (g == 0) { G0(OP) } else if (g == 1) { G1(OP) } else if (g == 2) { G2(OP) } else { G3(OP) }

#define OPW(P,A,I) wdst[I] = __ldg(wrow + P * 64);
#define OPC(P,A,I) path_compute<P>(xs, zs, wreg[I], acc + A, c);
#define OPS(P,A,I) path_store<P>(node, c, acc + A);

// ---------------- edge + scatter kernel: one CTA per destination node ----------------
__global__ __launch_bounds__(256)
void edge_kernel(const float* __restrict__ x0, const float* __restrict__ x1,
                 const float* __restrict__ x2, const float* __restrict__ x3,
                 const float* __restrict__ ws, const int* __restrict__ eidx)
{
    __shared__ __align__(16) float xsb[2][1024];   // transposed: [l*64 + c] per degree block
    __shared__ __align__(16) float zsb[2][ZPADN];
    __shared__ int elist[ECAP];
    __shared__ int scanb[256];
    __shared__ int s_ne;

    const int node = blockIdx.x;
    const int tid  = threadIdx.x;
    const int* srcA = eidx;
    const int* dstA = eidx + E_EDGES;

    // ---- deterministic compaction of in-edges ----
    int cnt = 0;
    #pragma unroll
    for (int j = 0; j < E_EDGES / 256; j++)
        cnt += (dstA[tid + j * 256] == node) ? 1 : 0;
    scanb[tid] = cnt;
    __syncthreads();
    for (int off = 1; off < 256; off <<= 1) {
        int v = (tid >= off) ? scanb[tid - off] : 0;
        __syncthreads();
        scanb[tid] += v;
        __syncthreads();
    }
    int pos = scanb[tid] - cnt;
    if (tid == 255) s_ne = (scanb[255] < ECAP) ? scanb[255] : ECAP;
    __syncthreads();
    #pragma unroll
    for (int j = 0; j < E_EDGES / 256; j++) {
        int e = tid + j * 256;
        if (dstA[e] == node) { if (pos < ECAP) elist[pos] = e; pos++; }
    }
    __syncthreads();
    const int ne = s_ne;

    const int g = tid >> 6;
    const int c = tid & 63;

    float acc[44];
    #pragma unroll
    for (int i = 0; i < 44; i++) acc[i] = 0.f;
    float wreg[10], wnx[10];
    float4 xr = make_float4(0, 0, 0, 0);
    float4 zr = make_float4(0, 0, 0, 0), zr2 = make_float4(0, 0, 0, 0);

    auto ldx = [&](int s) -> float4 {
        int i4 = tid * 4;
        if (tid < 16)   return *(const float4*)(x0 + s * 64  + i4);
        if (tid < 64)   return *(const float4*)(x1 + s * 192 + (i4 - 64));
        if (tid < 144)  return *(const float4*)(x2 + s * 320 + (i4 - 256));
        return                 *(const float4*)(x3 + s * 448 + (i4 - 576));
    };
    auto ldz = [&](int e) {
        const float* zrow = g_Z + (size_t)e * ZPADN;
        zr = *(const float4*)(zrow + tid * 4);
        if (tid < 4) zr2 = *(const float4*)(zrow + 1024 + tid * 4);
    };
    auto commit = [&](int b) {
        float v[4] = {xr.x, xr.y, xr.z, xr.w};
        if (tid < 16) {
            *(float4*)&xsb[b][tid * 4] = xr;
        } else if (tid < 64) {
            int idx = tid * 4 - 64;
            #pragma unroll
            for (int j = 0; j < 4; j++) {
                int id = idx + j;
                xsb[b][64 + (id % 3) * 64 + id / 3] = v[j];
            }
        } else if (tid < 144) {
            int idx = tid * 4 - 256;
            #pragma unroll
            for (int j = 0; j < 4; j++) {
                int id = idx + j;
                xsb[b][256 + (id % 5) * 64 + id / 5] = v[j];
            }
        } else {
            int idx = tid * 4 - 576;
            #pragma unroll
            for (int j = 0; j < 4; j++) {
                int id = idx + j;
                xsb[b][576 + (id % 7) * 64 + id / 7] = v[j];
            }
        }
        *(float4*)&zsb[b][tid * 4] = zr;
        if (tid < 4) *(float4*)&zsb[b][1024 + tid * 4] = zr2;
    };

    if (ne > 0) {
        int e0 = elist[0];
        xr = ldx(srcA[e0]);
        ldz(e0);
        const float* wrow = ws + (size_t)e0 * WS_STRIDE + c;
        float* wdst = wreg;
        FORG(OPW)
    }

    for (int k = 0; k < ne; k++) {
        const int b = k & 1;
        commit(b);
        __syncthreads();

        if (k + 1 < ne) {
            int e1 = elist[k + 1];
            xr = ldx(srcA[e1]);
            ldz(e1);
            const float* wrow = ws + (size_t)e1 * WS_STRIDE + c;
            float* wdst = wnx;
            FORG(OPW)
        }

        const float* xs = xsb[b];
        const float* zs = zsb[b];
        FORG(OPC)

        #pragma unroll
        for (int i = 0; i < 10; i++) wreg[i] = wnx[i];
    }

    FORG(OPS)
}

// ---------------- output GEMM: tf32 mma.sync, BM=128 BN=64 BK=16, dbuf ----------------
__global__ __launch_bounds__(256)
void gemm_kernel(const float* __restrict__ W0, const float* __restrict__ W1,
                 const float* __restrict__ W2, const float* __restrict__ W3,
                 float* __restrict__ out)
{
    __shared__ unsigned As[2][16][136];   // tf32 bits, [k][m], stride 136 (frag LDS conflict-free)
    __shared__ unsigned Bs[2][16][72];    // tf32 bits, [k][n], stride 72  (frag LDS conflict-free)

    const int blk = blockIdx.x, tid = threadIdx.x;
    int l3, t0;
    if (blk < 16)       { l3 = 0; t0 = 0; }
    else if (blk < 64)  { l3 = 1; t0 = 16; }
    else if (blk < 144) { l3 = 2; t0 = 64; }
    else                { l3 = 3; t0 = 144; }
    const int rowTile = blk - t0;

    const int  KA[4]  = {256, 576, 704, 640};
    const long MBl[4] = {0L, 524288L, 4063232L, 11272192L};
    const long OB[4]  = {0L, 131072L, 524288L, 1179648L};
    const int  K  = KA[l3];
    const int  ld = 2 * l3 + 1;
    const float* A = g_M + MBl[l3] + (long)rowTile * 128 * K;
    const float* B = (l3 == 0) ? W0 : (l3 == 1) ? W1 : (l3 == 2) ? W2 : W3;
    float* Ob = out + OB[l3];

    const int arow = tid >> 1, ac0 = (tid & 1) * 8;     // A: 128 rows x 16 k
    const int brow = tid >> 4, bc0 = (tid & 15) * 4;    // B: 16 k x 64 n
    const int w = tid >> 5, lane = tid & 31;
    const int gid = lane >> 2, tig = lane & 3;
    const int m0 = w * 16;

    float acc[8][4];
    #pragma unroll
    for (int i = 0; i < 8; i++)
        #pragma unroll
        for (int j = 0; j < 4; j++) acc[i][j] = 0.f;

    float4 a0, a1, b0;
    auto ldtile = [&](int k0) {
        a0 = *(const float4*)(A + (long)arow * K + k0 + ac0);
        a1 = *(const float4*)(A + (long)arow * K + k0 + ac0 + 4);
        b0 = *(const float4*)(B + (long)(k0 + brow) * 64 + bc0);
    };
    ldtile(0);

    const int nt = K / 16;
    for (int t = 0; t < nt; t++) {
        const int b = t & 1;
        As[b][ac0 + 0][arow] = tf32cvt(a0.x); As[b][ac0 + 1][arow] = tf32cvt(a0.y);
        As[b][ac0 + 2][arow] = tf32cvt(a0.z); As[b][ac0 + 3][arow] = tf32cvt(a0.w);
        As[b][ac0 + 4][arow] = tf32cvt(a1.x); As[b][ac0 + 5][arow] = tf32cvt(a1.y);
        As[b][ac0 + 6][arow] = tf32cvt(a1.z); As[b][ac0 + 7][arow] = tf32cvt(a1.w);
        {
            uint4 bb;
            bb.x = tf32cvt(b0.x); bb.y = tf32cvt(b0.y);
            bb.z = tf32cvt(b0.z); bb.w = tf32cvt(b0.w);
            *(uint4*)&Bs[b][brow][bc0] = bb;
        }
        __syncthreads();

        if (t + 1 < nt) ldtile((t + 1) * 16);

        #pragma unroll
        for (int kf = 0; kf < 16; kf += 8) {
            unsigned ua0 = As[b][kf + tig][m0 + gid];
            unsigned ua1 = As[b][kf + tig][m0 + gid + 8];
            unsigned ua2 = As[b][kf + tig + 4][m0 + gid];
            unsigned ua3 = As[b][kf + tig + 4][m0 + gid + 8];
            #pragma unroll
            for (int nf = 0; nf < 8; nf++) {
                unsigned ub0 = Bs[b][kf + tig][nf * 8 + gid];
                unsigned ub1 = Bs[b][kf + tig + 4][nf * 8 + gid];
                mma_tf32(acc[nf], ua0, ua1, ua2, ua3, ub0, ub1);
            }
        }
        __syncthreads();
    }

    // epilogue: C[r][h] -> out[node][h][m], r = node*ld + m
    const int r1 = rowTile * 128 + m0 + gid;
    const int r2 = r1 + 8;
    const int n1 = r1 / ld, m1 = r1 - n1 * ld;
    const int n2 = r2 / ld, m2 = r2 - n2 * ld;
    float* o1 = Ob + (long)n1 * 64 * ld + m1;
    float* o2 = Ob + (long)n2 * 64 * ld + m2;
    #pragma unroll
    for (int nf = 0; nf < 8; nf++) {
        int h = nf * 8 + tig * 2;
        o1[(long)h * ld]       = acc[nf][0];
        o1[(long)(h + 1) * ld] = acc[nf][1];
        o2[(long)h * ld]       = acc[nf][2];
        o2[(long)(h + 1) * ld] = acc[nf][3];
    }
}

// ---------------- host: regenerate numpy CG constants + z metadata ----------------
static void build_host_tables(float* cg, int4* zm)
{
    uint32_t mt[624]; int mti;
    uint32_t sd = 1234u;
    for (int i = 0; i < 624; i++) {
        mt[i] = sd;
        sd = 1812433253u * (sd ^ (sd >> 30)) + (uint32_t)i + 1u;
    }
    mti = 624;
    auto mt_next = [&]() -> uint32_t {
        if (mti >= 624) {
            for (int i = 0; i < 624; i++) {
                uint32_t y = (mt[i] & 0x80000000u) | (mt[(i + 1) % 624] & 0x7fffffffu);
                mt[i] = mt[(i + 397) % 624] ^ (y >> 1) ^ ((y & 1u) ? 0x9908b0dfu : 0u);
            }
            mti = 0;
        }
        uint32_t y = mt[mti++];
        y ^= y >> 11; y ^= (y << 7) & 0x9d2c5680u;
        y ^= (y << 15) & 0xefc60000u; y ^= y >> 18;
        return y;
    };
    auto rk_double = [&]() -> double {
        uint32_t a = mt_next() >> 5, b = mt_next() >> 6;
        return ((double)a * 67108864.0 + (double)b) / 9007199254740992.0;
    };
    bool has_g = false; double gch = 0.0;
    auto gauss = [&]() -> double {
        if (has_g) { has_g = false; return gch; }
        double x1, x2, r2;
        do {
            x1 = 2.0 * rk_double() - 1.0;
            x2 = 2.0 * rk_double() - 1.0;
            r2 = x1 * x1 + x2 * x2;
        } while (r2 >= 1.0 || r2 == 0.0);
        double f = sqrt(-2.0 * log(r2) / r2);
        gch = f * x1; has_g = true;
        return f * x2;
    };

    const int ybase[4] = {0, 1, 4, 9};
    int cgoff = 0, zoff = 0, zpoff = 0;
    for (int a = 0; a < 4; a++)
        for (int b = 0; b < 4; b++) {
            int lo = a > b ? a - b : b - a, hi = (a + b < 3) ? a + b : 3;
            for (int c = lo; c <= hi; c++) {
                int d1 = 2 * a + 1, d2 = 2 * b + 1, d3 = 2 * c + 1;
                int pitch = (d3 <= 3) ? 4 : 8;
                int n = d1 * d2 * d3;
                for (int t = 0; t < n; t++) cg[cgoff + t] = (float)(gauss() * 0.2);
                for (int l = 0; l < d1; l++)
                    for (int nn = 0; nn < d3; nn++) {
                        int j = zoff + l * d3 + nn;
                        zm[j].x = cgoff + l * d2 * d3 + nn;
                        zm[j].y = ybase[b] | (d3 << 8) | (d2 << 16);
                        zm[j].z = zpoff + l * pitch + nn;
                        zm[j].w = 0;
                    }
                cgoff += n; zoff += d1 * d3; zpoff += d1 * pitch;
            }
        }
}

extern "C" void kernel_launch(void* const* d_in, const int* in_sizes, int n_in,
                              void* d_out, int out_size)
{
    static float h_cg[NCG];
    static int4  h_zm[NZ];
    build_host_tables(h_cg, h_zm);

    cudaMemcpyToSymbolAsync(g_CG, h_cg, sizeof(h_cg), 0, cudaMemcpyHostToDevice, 0);
    cudaMemcpyToSymbolAsync(g_ZM, h_zm, sizeof(h_zm), 0, cudaMemcpyHostToDevice, 0);

    const float *x[4], *y[4], *wl[4], *wsP;
    const int* ei;
    if (n_in >= 14 && in_sizes[1] == E_EDGES) {
        for (int l = 0; l < 4; l++) {
            x[l]  = (const float*)d_in[3 * l + 0];
            y[l]  = (const float*)d_in[3 * l + 1];
            wl[l] = (const float*)d_in[3 * l + 2];
        }
        wsP = (const float*)d_in[12];
        ei  = (const int*)d_in[13];
    } else {
        for (int l = 0; l < 4; l++) {
            x[l]  = (const float*)d_in[l];
            y[l]  = (const float*)d_in[4 + l];
            wl[l] = (const float*)d_in[9 + l];
        }
        wsP = (const float*)d_in[8];
        ei  = (const int*)d_in[13];
    }

    z_kernel<<<E_EDGES / 16, 256>>>(y[0], y[1], y[2], y[3]);
    edge_kernel<<<N_NODES, 256>>>(x[0], x[1], x[2], x[3], wsP, ei);
    gemm_kernel<<<256, 256>>>(wl[0], wl[1], wl[2], wl[3], (float*)d_out);
    (void)out_size;
}